// round 1
// baseline (speedup 1.0000x reference)
#include <cuda_runtime.h>
#include <cstdint>

#define DIMC   512
#define IDIM   1536
#define BATCH  16
#define TLEN   2048
#define MTOT   (BATCH*TLEN)   // 32768
#define KCONV  7

// ---------------- scratch (static device globals; allocation-free) ----------
__device__ float g_y[(size_t)MTOT * DIMC];     // conv out, then LN in-place (67MB)
__device__ float g_h[(size_t)MTOT * IDIM];     // GEMM1 out (201MB)
__device__ float g_y2[(size_t)MTOT * DIMC];    // GEMM2 out (67MB)
__device__ float g_part[4 * BATCH * IDIM];     // GRN partial sums
__device__ float g_alpha[BATCH * IDIM];        // GRN fused scale

// ---------------- helpers ---------------------------------------------------
__device__ __forceinline__ uint32_t f2tf(float x) {
    uint32_t r; asm("cvt.rna.tf32.f32 %0, %1;" : "=r"(r) : "f"(x)); return r;
}
__device__ __forceinline__ void mma8(float* d, const uint32_t* a, const uint32_t* b) {
    asm volatile("mma.sync.aligned.m16n8k8.row.col.f32.tf32.tf32.f32 "
        "{%0,%1,%2,%3}, {%4,%5,%6,%7}, {%8,%9}, {%0,%1,%2,%3};\n"
        : "+f"(d[0]), "+f"(d[1]), "+f"(d[2]), "+f"(d[3])
        : "r"(a[0]), "r"(a[1]), "r"(a[2]), "r"(a[3]), "r"(b[0]), "r"(b[1]));
}
__device__ __forceinline__ float gelu_exact(float x) {
    return 0.5f * x * (1.f + erff(x * 0.70710678118654752440f));
}

// ---------------- 1. depthwise conv + bias + transpose ----------------------
// x[B,C,T] -> g_y[(b*T+t)*C + c]
__global__ void k_dwconv(const float* __restrict__ x, const float* __restrict__ w,
                         const float* __restrict__ bias) {
    __shared__ float sx[32][41];
    const int t0 = blockIdx.x * 32;
    const int c0 = blockIdx.y * 32;
    const int bb = blockIdx.z;
    const int tx = threadIdx.x;     // 32
    const int ty = threadIdx.y;     // 8
    const float* xb = x + ((size_t)bb * DIMC + c0) * TLEN;

#pragma unroll
    for (int j = 0; j < 4; j++) {
        int c = ty + j * 8;
        int t = t0 - 3 + tx;
        sx[c][tx] = (t >= 0 && t < TLEN) ? xb[(size_t)c * TLEN + t] : 0.f;
        if (tx < 6) {
            int t2 = t0 + 29 + tx;  // t0 - 3 + 32 + tx
            sx[c][32 + tx] = (t2 >= 0 && t2 < TLEN) ? xb[(size_t)c * TLEN + t2] : 0.f;
        }
    }
    __syncthreads();

    const int c = c0 + tx;
    float wr[KCONV];
#pragma unroll
    for (int k = 0; k < KCONV; k++) wr[k] = w[c * KCONV + k];
    const float bv = bias[c];

#pragma unroll
    for (int j = 0; j < 4; j++) {
        int tl = ty * 4 + j;
        float acc = bv;
#pragma unroll
        for (int k = 0; k < KCONV; k++) acc += wr[k] * sx[tx][tl + k];
        g_y[((size_t)bb * TLEN + t0 + tl) * DIMC + c] = acc;
    }
}

// ---------------- 2. LayerNorm over C (in-place on g_y) ---------------------
__global__ void k_ln(const float* __restrict__ gam, const float* __restrict__ bet) {
    const size_t row = blockIdx.x;
    float4* p = (float4*)(g_y + row * DIMC);
    const int tid = threadIdx.x;            // 128 threads, 4 elems each
    float4 v = p[tid];
    float s = v.x + v.y + v.z + v.w;
    float q = v.x * v.x + v.y * v.y + v.z * v.z + v.w * v.w;
#pragma unroll
    for (int o = 16; o; o >>= 1) {
        s += __shfl_xor_sync(0xffffffffu, s, o);
        q += __shfl_xor_sync(0xffffffffu, q, o);
    }
    __shared__ float sh[8];
    if ((tid & 31) == 0) { sh[tid >> 5] = s; sh[(tid >> 5) + 4] = q; }
    __syncthreads();
    const float S = sh[0] + sh[1] + sh[2] + sh[3];
    const float Q = sh[4] + sh[5] + sh[6] + sh[7];
    const float mu = S * (1.f / DIMC);
    const float var = Q * (1.f / DIMC) - mu * mu;
    const float inv = rsqrtf(var + 1e-6f);
    const float4 gg = ((const float4*)gam)[tid];
    const float4 bb = ((const float4*)bet)[tid];
    v.x = (v.x - mu) * inv * gg.x + bb.x;
    v.y = (v.y - mu) * inv * gg.y + bb.y;
    v.z = (v.z - mu) * inv * gg.z + bb.z;
    v.w = (v.w - mu) * inv * gg.w + bb.w;
    p[tid] = v;
}

// ---------------- 3/5. TF32 GEMM, 128x128x16 tiles, double buffered ---------
// SEL==0: g_h = GELU(g_y * w1^T + b1)        (K=512,  N=1536)
// SEL==1: g_y2 = (g_h*alpha+beta) * w2^T + b2 (K=1536, N=512)
template <int SEL>
__global__ __launch_bounds__(256)
void k_gemm(const float* __restrict__ W, const float* __restrict__ bias,
            const float* __restrict__ beta) {
    constexpr int K = (SEL == 0) ? DIMC : IDIM;
    constexpr int N = (SEL == 0) ? IDIM : DIMC;
    constexpr int KT = K / 16;
    constexpr int BKP = 20;   // pad: conflict-free fragment LDS
    const float* __restrict__ A = (SEL == 0) ? g_y : g_h;
    float* __restrict__ C = (SEL == 0) ? g_h : g_y2;

    __shared__ uint32_t sA[2][128 * BKP];
    __shared__ uint32_t sB[2][128 * BKP];

    const int tid = threadIdx.x;
    const int m0 = blockIdx.y * 128;
    const int n0 = blockIdx.x * 128;
    const int lane = tid & 31;
    const int warp = tid >> 5;
    const int wm = warp >> 2;   // 0..1 -> 64 rows
    const int wn = warp & 3;    // 0..3 -> 32 cols

    const int lrow = tid >> 2;          // 0..63 (then +64)
    const int lcol = (tid & 3) * 4;     // 0,4,8,12

    const float* Ap = A + (size_t)(m0 + lrow) * K + lcol;
    const float* Bp = W + (size_t)(n0 + lrow) * K + lcol;
    const float* alp = g_alpha + (size_t)(m0 >> 11) * IDIM;  // b = m0/2048

    float4 ra0, ra1, rb0, rb1;
    float acc[4][4][4];
#pragma unroll
    for (int i = 0; i < 4; i++)
#pragma unroll
        for (int j = 0; j < 4; j++)
#pragma unroll
            for (int l = 0; l < 4; l++) acc[i][j][l] = 0.f;

    auto loadG = [&](int kt) {
        const float* a0 = Ap + kt * 16;
        ra0 = *(const float4*)a0;
        ra1 = *(const float4*)(a0 + (size_t)64 * K);
        const float* b0 = Bp + kt * 16;
        rb0 = *(const float4*)b0;
        rb1 = *(const float4*)(b0 + (size_t)64 * K);
        if (SEL == 1) {
            int k = kt * 16 + lcol;
            float4 al = *(const float4*)(alp + k);
            float4 be = *(const float4*)(beta + k);
            ra0.x = fmaf(ra0.x, al.x, be.x); ra0.y = fmaf(ra0.y, al.y, be.y);
            ra0.z = fmaf(ra0.z, al.z, be.z); ra0.w = fmaf(ra0.w, al.w, be.w);
            ra1.x = fmaf(ra1.x, al.x, be.x); ra1.y = fmaf(ra1.y, al.y, be.y);
            ra1.z = fmaf(ra1.z, al.z, be.z); ra1.w = fmaf(ra1.w, al.w, be.w);
        }
    };
    auto storeS = [&](int buf) {
        uint32_t* pa = &sA[buf][lrow * BKP + lcol];
        pa[0] = f2tf(ra0.x); pa[1] = f2tf(ra0.y); pa[2] = f2tf(ra0.z); pa[3] = f2tf(ra0.w);
        pa += 64 * BKP;
        pa[0] = f2tf(ra1.x); pa[1] = f2tf(ra1.y); pa[2] = f2tf(ra1.z); pa[3] = f2tf(ra1.w);
        uint32_t* pb = &sB[buf][lrow * BKP + lcol];
        pb[0] = f2tf(rb0.x); pb[1] = f2tf(rb0.y); pb[2] = f2tf(rb0.z); pb[3] = f2tf(rb0.w);
        pb += 64 * BKP;
        pb[0] = f2tf(rb1.x); pb[1] = f2tf(rb1.y); pb[2] = f2tf(rb1.z); pb[3] = f2tf(rb1.w);
    };
    auto compute = [&](int buf) {
#pragma unroll
        for (int ks = 0; ks < 2; ks++) {
            uint32_t af[4][4], bf[4][2];
            const int kc = ks * 8 + (lane & 3);
            const int rA = wm * 64 + (lane >> 2);
#pragma unroll
            for (int mt = 0; mt < 4; mt++) {
                const uint32_t* p = &sA[buf][(rA + mt * 16) * BKP + kc];
                af[mt][0] = p[0]; af[mt][1] = p[8 * BKP];
                af[mt][2] = p[4]; af[mt][3] = p[8 * BKP + 4];
            }
            const int rB = wn * 32 + (lane >> 2);
#pragma unroll
            for (int nt = 0; nt < 4; nt++) {
                const uint32_t* p = &sB[buf][(rB + nt * 8) * BKP + kc];
                bf[nt][0] = p[0]; bf[nt][1] = p[4];
            }
#pragma unroll
            for (int mt = 0; mt < 4; mt++)
#pragma unroll
                for (int nt = 0; nt < 4; nt++)
                    mma8(acc[mt][nt], af[mt], bf[nt]);
        }
    };

    loadG(0);
    storeS(0);
    __syncthreads();
    int buf = 0;
#pragma unroll 2
    for (int kt = 0; kt < KT; kt++) {
        if (kt + 1 < KT) loadG(kt + 1);
        compute(buf);
        if (kt + 1 < KT) {
            storeS(buf ^ 1);
            __syncthreads();
            buf ^= 1;
        }
    }

    // epilogue
#pragma unroll
    for (int mt = 0; mt < 4; mt++) {
        int row = m0 + wm * 64 + mt * 16 + (lane >> 2);
#pragma unroll
        for (int nt = 0; nt < 4; nt++) {
            int col = n0 + wn * 32 + nt * 8 + 2 * (lane & 3);
            float b0v = bias[col], b1v = bias[col + 1];
            float v0 = acc[mt][nt][0] + b0v;
            float v1 = acc[mt][nt][1] + b1v;
            float v2 = acc[mt][nt][2] + b0v;
            float v3 = acc[mt][nt][3] + b1v;
            if (SEL == 0) {
                v0 = gelu_exact(v0); v1 = gelu_exact(v1);
                v2 = gelu_exact(v2); v3 = gelu_exact(v3);
            }
            *(float2*)&C[(size_t)row * N + col] = make_float2(v0, v1);
            *(float2*)&C[(size_t)(row + 8) * N + col] = make_float2(v2, v3);
        }
    }
}

// ---------------- 4a. GRN partial sums: sum_t h^2 ---------------------------
__global__ void k_grn_partial() {
    const int i = blockIdx.x * 256 + threadIdx.x;   // gridDim.x = 6
    const int tc = blockIdx.y;                      // 4 chunks of 512 t
    const int b = blockIdx.z;
    const float* p = g_h + ((size_t)b * TLEN + tc * 512) * IDIM + i;
    float s = 0.f;
#pragma unroll 8
    for (int t = 0; t < 512; t++) {
        float v = p[(size_t)t * IDIM];
        s += v * v;
    }
    g_part[((size_t)tc * BATCH + b) * IDIM + i] = s;
}

// ---------------- 4b. GRN alpha ---------------------------------------------
__global__ void k_grn_alpha(const float* __restrict__ gg) {
    const int b = blockIdx.x;
    const int tid = threadIdx.x;   // 256
    __shared__ float sgx[IDIM];
    __shared__ float red[8];
    float local = 0.f;
    for (int i = tid; i < IDIM; i += 256) {
        float s = g_part[(0 * BATCH + b) * IDIM + i] + g_part[(1 * BATCH + b) * IDIM + i]
                + g_part[(2 * BATCH + b) * IDIM + i] + g_part[(3 * BATCH + b) * IDIM + i];
        float gx = sqrtf(s);
        sgx[i] = gx;
        local += gx;
    }
#pragma unroll
    for (int o = 16; o; o >>= 1) local += __shfl_xor_sync(0xffffffffu, local, o);
    if ((tid & 31) == 0) red[tid >> 5] = local;
    __syncthreads();
    float tot = red[0] + red[1] + red[2] + red[3] + red[4] + red[5] + red[6] + red[7];
    const float inv = 1.f / (tot * (1.f / IDIM) + 1e-6f);
    for (int i = tid; i < IDIM; i += 256)
        g_alpha[b * IDIM + i] = 1.f + gg[i] * sgx[i] * inv;
}

// ---------------- 6. transpose + residual -----------------------------------
__global__ void k_out(const float* __restrict__ x, float* __restrict__ out) {
    __shared__ float s[32][33];
    const int t0 = blockIdx.x * 32;
    const int c0 = blockIdx.y * 32;
    const int b = blockIdx.z;
    const int tx = threadIdx.x, ty = threadIdx.y;
#pragma unroll
    for (int j = 0; j < 4; j++) {
        int t = ty + j * 8;
        s[t][tx] = g_y2[((size_t)b * TLEN + t0 + t) * DIMC + c0 + tx];
    }
    __syncthreads();
#pragma unroll
    for (int j = 0; j < 4; j++) {
        int c = ty + j * 8;
        size_t o = ((size_t)b * DIMC + c0 + c) * TLEN + t0 + tx;
        out[o] = x[o] + s[tx][c];
    }
}

// ---------------- launch ----------------------------------------------------
extern "C" void kernel_launch(void* const* d_in, const int* in_sizes, int n_in,
                              void* d_out, int out_size) {
    (void)in_sizes; (void)n_in; (void)out_size;
    const float* x     = (const float*)d_in[0];
    const float* dw_w  = (const float*)d_in[1];
    const float* dw_b  = (const float*)d_in[2];
    const float* ln_g  = (const float*)d_in[3];
    const float* ln_b  = (const float*)d_in[4];
    const float* w1    = (const float*)d_in[5];
    const float* b1    = (const float*)d_in[6];
    const float* grn_g = (const float*)d_in[7];
    const float* grn_b = (const float*)d_in[8];
    const float* w2    = (const float*)d_in[9];
    const float* b2    = (const float*)d_in[10];
    float* out = (float*)d_out;

    k_dwconv<<<dim3(TLEN / 32, DIMC / 32, BATCH), dim3(32, 8)>>>(x, dw_w, dw_b);
    k_ln<<<MTOT, 128>>>(ln_g, ln_b);
    k_gemm<0><<<dim3(IDIM / 128, MTOT / 128), 256>>>(w1, b1, nullptr);
    k_grn_partial<<<dim3(IDIM / 256, 4, BATCH), 256>>>();
    k_grn_alpha<<<BATCH, 256>>>(grn_g);
    k_gemm<1><<<dim3(DIMC / 128, MTOT / 128), 256>>>(w2, b2, grn_b);
    k_out<<<dim3(TLEN / 32, DIMC / 32, BATCH), dim3(32, 8)>>>(x, out);
}

// round 4
// speedup vs baseline: 1.1880x; 1.1880x over previous
#include <cuda_runtime.h>
#include <cstdint>

#define DIMC   512
#define IDIM   1536
#define BATCH  16
#define TLEN   2048
#define MTOT   (BATCH*TLEN)   // 32768
#define KCONV  7
#define NCHUNK 16

// ---------------- scratch ----------------------------------------------------
__device__ float g_y[(size_t)MTOT * DIMC];      // conv out, then LN in-place
__device__ float g_h[(size_t)MTOT * IDIM];      // GEMM1 out
__device__ float g_y2[(size_t)MTOT * DIMC];     // GEMM2 out
__device__ float g_part[NCHUNK * BATCH * IDIM]; // GRN partial sums
__device__ float g_alpha[BATCH * IDIM];         // GRN fused scale

// ---------------- helpers ----------------------------------------------------
__device__ __forceinline__ uint32_t f2tf(float x) {
    uint32_t r; asm("cvt.rna.tf32.f32 %0, %1;" : "=r"(r) : "f"(x)); return r;
}
__device__ __forceinline__ void mma8(float* d, const uint32_t* a, const uint32_t* b) {
    asm volatile("mma.sync.aligned.m16n8k8.row.col.f32.tf32.tf32.f32 "
        "{%0,%1,%2,%3}, {%4,%5,%6,%7}, {%8,%9}, {%0,%1,%2,%3};\n"
        : "+f"(d[0]), "+f"(d[1]), "+f"(d[2]), "+f"(d[3])
        : "r"(a[0]), "r"(a[1]), "r"(a[2]), "r"(a[3]), "r"(b[0]), "r"(b[1]));
}
__device__ __forceinline__ float gelu_exact(float x) {
    return 0.5f * x * (1.f + erff(x * 0.70710678118654752440f));
}
__device__ __forceinline__ uint32_t smem_u32(const void* p) {
    uint32_t a;
    asm("{ .reg .u64 t; cvta.to.shared.u64 t, %1; cvt.u32.u64 %0, t; }" : "=r"(a) : "l"(p));
    return a;
}
__device__ __forceinline__ void cpa16(void* d, const void* s) {
    asm volatile("cp.async.cg.shared.global [%0], [%1], 16;"
                 :: "r"(smem_u32(d)), "l"(s) : "memory");
}

// ---------------- 1. depthwise conv + bias + transpose ----------------------
__global__ void k_dwconv(const float* __restrict__ x, const float* __restrict__ w,
                         const float* __restrict__ bias) {
    __shared__ float sx[32][41];
    const int t0 = blockIdx.x * 32;
    const int c0 = blockIdx.y * 32;
    const int bb = blockIdx.z;
    const int tx = threadIdx.x;
    const int ty = threadIdx.y;
    const float* xb = x + ((size_t)bb * DIMC + c0) * TLEN;

#pragma unroll
    for (int j = 0; j < 4; j++) {
        int c = ty + j * 8;
        int t = t0 - 3 + tx;
        sx[c][tx] = (t >= 0 && t < TLEN) ? xb[(size_t)c * TLEN + t] : 0.f;
        if (tx < 6) {
            int t2 = t0 + 29 + tx;
            sx[c][32 + tx] = (t2 >= 0 && t2 < TLEN) ? xb[(size_t)c * TLEN + t2] : 0.f;
        }
    }
    __syncthreads();

    const int c = c0 + tx;
    float wr[KCONV];
#pragma unroll
    for (int k = 0; k < KCONV; k++) wr[k] = w[c * KCONV + k];
    const float bv = bias[c];

#pragma unroll
    for (int j = 0; j < 4; j++) {
        int tl = ty * 4 + j;
        float acc = bv;
#pragma unroll
        for (int k = 0; k < KCONV; k++) acc += wr[k] * sx[tx][tl + k];
        g_y[((size_t)bb * TLEN + t0 + tl) * DIMC + c] = acc;
    }
}

// ---------------- 2. LayerNorm over C (in-place) -----------------------------
__global__ void k_ln(const float* __restrict__ gam, const float* __restrict__ bet) {
    const size_t row = blockIdx.x;
    float4* p = (float4*)(g_y + row * DIMC);
    const int tid = threadIdx.x;
    float4 v = p[tid];
    float s = v.x + v.y + v.z + v.w;
    float q = v.x * v.x + v.y * v.y + v.z * v.z + v.w * v.w;
#pragma unroll
    for (int o = 16; o; o >>= 1) {
        s += __shfl_xor_sync(0xffffffffu, s, o);
        q += __shfl_xor_sync(0xffffffffu, q, o);
    }
    __shared__ float sh[8];
    if ((tid & 31) == 0) { sh[tid >> 5] = s; sh[(tid >> 5) + 4] = q; }
    __syncthreads();
    const float S = sh[0] + sh[1] + sh[2] + sh[3];
    const float Q = sh[4] + sh[5] + sh[6] + sh[7];
    const float mu = S * (1.f / DIMC);
    const float var = Q * (1.f / DIMC) - mu * mu;
    const float inv = rsqrtf(var + 1e-6f);
    const float4 gg = ((const float4*)gam)[tid];
    const float4 bb = ((const float4*)bet)[tid];
    v.x = (v.x - mu) * inv * gg.x + bb.x;
    v.y = (v.y - mu) * inv * gg.y + bb.y;
    v.z = (v.z - mu) * inv * gg.z + bb.z;
    v.w = (v.w - mu) * inv * gg.w + bb.w;
    p[tid] = v;
}

// ---------------- 3/5. TF32 mma.sync GEMM + cp.async 4-stage pipeline -------
// SEL==0: g_h  = GELU(g_y * w1^T + b1)          (K=512,  N=1536)
// SEL==1: g_y2 = (g_h*alpha+beta) * w2^T + b2   (K=1536, N=512)
template <int SEL>
__global__ __launch_bounds__(256, 2)
void k_gemm(const float* __restrict__ W, const float* __restrict__ bias,
            const float* __restrict__ beta) {
    constexpr int K   = (SEL == 0) ? DIMC : IDIM;
    constexpr int N   = (SEL == 0) ? IDIM : DIMC;
    constexpr int KT  = K / 16;
    constexpr int BKP = 20;               // padded row: conflict-free fragment LDS
    constexpr int STG = 4;
    constexpr int STW = 128 * BKP;        // words per stage per operand
    const float* __restrict__ A = (SEL == 0) ? g_y : g_h;
    float* __restrict__ C = (SEL == 0) ? g_h : g_y2;

    extern __shared__ float sm[];
    float* sA = sm;                       // STG * STW
    float* sB = sm + STG * STW;           // STG * STW
    float* s_al = sm + 2 * STG * STW;     // K (SEL==1)
    float* s_be = s_al + K;               // K (SEL==1)

    const int tid = threadIdx.x;
    const int lane = tid & 31;
    const int warp = tid >> 5;
    const int wm = warp >> 2;             // 0..1 -> 64-row half
    const int wn = warp & 3;              // 0..3 -> 32-col quarter
    const int m0 = blockIdx.y * 128;
    const int n0 = blockIdx.x * 128;

    if (SEL == 1) {
        const float* alp = g_alpha + (size_t)(m0 >> 11) * IDIM;
        for (int i = tid; i < K; i += 256) {
            s_al[i] = alp[i];
            s_be[i] = beta[i];
        }
    }

    const int frow = tid >> 2;            // 0..63
    const int fcol = tid & 3;             // float4 slot (16 floats/row)
    const float* Ag = A + (size_t)(m0 + frow) * K + fcol * 4;
    const float* Bg = W + (size_t)(n0 + frow) * K + fcol * 4;

    auto fill = [&](int kt) {
        const int st = kt & 3;
        float* da = &sA[st * STW + frow * BKP + fcol * 4];
        const float* ga = Ag + kt * 16;
        cpa16(da, ga);
        cpa16(da + 64 * BKP, ga + (size_t)64 * K);
        float* db = &sB[st * STW + frow * BKP + fcol * 4];
        const float* gb = Bg + kt * 16;
        cpa16(db, gb);
        cpa16(db + 64 * BKP, gb + (size_t)64 * K);
        asm volatile("cp.async.commit_group;" ::: "memory");
    };

    float acc[4][4][4];
#pragma unroll
    for (int i = 0; i < 4; i++)
#pragma unroll
        for (int j = 0; j < 4; j++)
#pragma unroll
            for (int l = 0; l < 4; l++) acc[i][j][l] = 0.f;

    fill(0); fill(1); fill(2);

    for (int kt = 0; kt < KT; kt++) {
        asm volatile("cp.async.wait_group 2;" ::: "memory");
        __syncthreads();
        if (kt + 3 < KT) fill(kt + 3);
        else asm volatile("cp.async.commit_group;" ::: "memory");

        const int st = kt & 3;
        const float* cA = &sA[st * STW];
        const float* cB = &sB[st * STW];
#pragma unroll
        for (int ks = 0; ks < 2; ks++) {
            const int kc = ks * 8 + (lane & 3);
            uint32_t af[4][4], bf[4][2];
            float al0, al1, be0, be1;
            if (SEL == 1) {
                const int kg = kt * 16 + kc;
                al0 = s_al[kg];     be0 = s_be[kg];
                al1 = s_al[kg + 4]; be1 = s_be[kg + 4];
            }
            const int rA = wm * 64 + (lane >> 2);
#pragma unroll
            for (int mt = 0; mt < 4; mt++) {
                const float* p = &cA[(rA + mt * 16) * BKP + kc];
                float a0 = p[0], a1 = p[8 * BKP], a2 = p[4], a3 = p[8 * BKP + 4];
                if (SEL == 1) {
                    a0 = fmaf(a0, al0, be0); a1 = fmaf(a1, al0, be0);
                    a2 = fmaf(a2, al1, be1); a3 = fmaf(a3, al1, be1);
                }
                af[mt][0] = f2tf(a0); af[mt][1] = f2tf(a1);
                af[mt][2] = f2tf(a2); af[mt][3] = f2tf(a3);
            }
            const int rB = wn * 32 + (lane >> 2);
#pragma unroll
            for (int nt = 0; nt < 4; nt++) {
                const float* p = &cB[(rB + nt * 8) * BKP + kc];
                bf[nt][0] = f2tf(p[0]); bf[nt][1] = f2tf(p[4]);
            }
#pragma unroll
            for (int mt = 0; mt < 4; mt++)
#pragma unroll
                for (int nt = 0; nt < 4; nt++)
                    mma8(acc[mt][nt], af[mt], bf[nt]);
        }
    }

    // epilogue (identical layout to round-1 verified code)
#pragma unroll
    for (int mt = 0; mt < 4; mt++) {
        int row = m0 + wm * 64 + mt * 16 + (lane >> 2);
#pragma unroll
        for (int nt = 0; nt < 4; nt++) {
            int col = n0 + wn * 32 + nt * 8 + 2 * (lane & 3);
            float b0v = bias[col], b1v = bias[col + 1];
            float v0 = acc[mt][nt][0] + b0v;
            float v1 = acc[mt][nt][1] + b1v;
            float v2 = acc[mt][nt][2] + b0v;
            float v3 = acc[mt][nt][3] + b1v;
            if (SEL == 0) {
                v0 = gelu_exact(v0); v1 = gelu_exact(v1);
                v2 = gelu_exact(v2); v3 = gelu_exact(v3);
            }
            *(float2*)&C[(size_t)row * N + col] = make_float2(v0, v1);
            *(float2*)&C[(size_t)(row + 8) * N + col] = make_float2(v2, v3);
        }
    }
}

// ---------------- 4a. GRN partial sums ---------------------------------------
__global__ void k_grn_partial() {
    const int i = blockIdx.x * 256 + threadIdx.x;
    const int tc = blockIdx.y;                      // NCHUNK chunks of TLEN/NCHUNK
    const int b = blockIdx.z;
    constexpr int TC = TLEN / NCHUNK;               // 128
    const float* p = g_h + ((size_t)b * TLEN + tc * TC) * IDIM + i;
    float s = 0.f;
#pragma unroll 8
    for (int t = 0; t < TC; t++) {
        float v = p[(size_t)t * IDIM];
        s += v * v;
    }
    g_part[((size_t)tc * BATCH + b) * IDIM + i] = s;
}

// ---------------- 4b. GRN alpha ----------------------------------------------
__global__ void k_grn_alpha(const float* __restrict__ gg) {
    const int b = blockIdx.x;
    const int tid = threadIdx.x;
    __shared__ float sgx[IDIM];
    __shared__ float red[8];
    float local = 0.f;
    for (int i = tid; i < IDIM; i += 256) {
        float s = 0.f;
#pragma unroll
        for (int tc = 0; tc < NCHUNK; tc++)
            s += g_part[((size_t)tc * BATCH + b) * IDIM + i];
        float gx = sqrtf(s);
        sgx[i] = gx;
        local += gx;
    }
#pragma unroll
    for (int o = 16; o; o >>= 1) local += __shfl_xor_sync(0xffffffffu, local, o);
    if ((tid & 31) == 0) red[tid >> 5] = local;
    __syncthreads();
    float tot = red[0] + red[1] + red[2] + red[3] + red[4] + red[5] + red[6] + red[7];
    const float inv = 1.f / (tot * (1.f / IDIM) + 1e-6f);
    for (int i = tid; i < IDIM; i += 256)
        g_alpha[b * IDIM + i] = 1.f + gg[i] * sgx[i] * inv;
}

// ---------------- 6. transpose + residual ------------------------------------
__global__ void k_out(const float* __restrict__ x, float* __restrict__ out) {
    __shared__ float s[32][33];
    const int t0 = blockIdx.x * 32;
    const int c0 = blockIdx.y * 32;
    const int b = blockIdx.z;
    const int tx = threadIdx.x, ty = threadIdx.y;
#pragma unroll
    for (int j = 0; j < 4; j++) {
        int t = ty + j * 8;
        s[t][tx] = g_y2[((size_t)b * TLEN + t0 + t) * DIMC + c0 + tx];
    }
    __syncthreads();
#pragma unroll
    for (int j = 0; j < 4; j++) {
        int c = ty + j * 8;
        size_t o = ((size_t)b * DIMC + c0 + c) * TLEN + t0 + tx;
        out[o] = x[o] + s[tx][c];
    }
}

// ---------------- launch ------------------------------------------------------
extern "C" void kernel_launch(void* const* d_in, const int* in_sizes, int n_in,
                              void* d_out, int out_size) {
    (void)in_sizes; (void)n_in; (void)out_size;
    const float* x     = (const float*)d_in[0];
    const float* dw_w  = (const float*)d_in[1];
    const float* dw_b  = (const float*)d_in[2];
    const float* ln_g  = (const float*)d_in[3];
    const float* ln_b  = (const float*)d_in[4];
    const float* w1    = (const float*)d_in[5];
    const float* b1    = (const float*)d_in[6];
    const float* grn_g = (const float*)d_in[7];
    const float* grn_b = (const float*)d_in[8];
    const float* w2    = (const float*)d_in[9];
    const float* b2    = (const float*)d_in[10];
    float* out = (float*)d_out;

    const int dyn0 = 4 * 128 * 20 * 4 * 2;              // 81920
    const int dyn1 = dyn0 + 2 * IDIM * 4;               // + alpha/beta tables
    cudaFuncSetAttribute(k_gemm<0>, cudaFuncAttributeMaxDynamicSharedMemorySize, dyn0);
    cudaFuncSetAttribute(k_gemm<1>, cudaFuncAttributeMaxDynamicSharedMemorySize, dyn1);

    k_dwconv<<<dim3(TLEN / 32, DIMC / 32, BATCH), dim3(32, 8)>>>(x, dw_w, dw_b);
    k_ln<<<MTOT, 128>>>(ln_g, ln_b);
    k_gemm<0><<<dim3(IDIM / 128, MTOT / 128), 256, dyn0>>>(w1, b1, nullptr);
    k_grn_partial<<<dim3(IDIM / 256, NCHUNK, BATCH), 256>>>();
    k_grn_alpha<<<BATCH, 256>>>(grn_g);
    k_gemm<1><<<dim3(DIMC / 128, MTOT / 128), 256, dyn1>>>(w2, b2, grn_b);
    k_out<<<dim3(TLEN / 32, DIMC / 32, BATCH), dim3(32, 8)>>>(x, out);
}

// round 5
// speedup vs baseline: 1.2596x; 1.0602x over previous
#include <cuda_runtime.h>
#include <cstdint>

#define DIMC   512
#define IDIM   1536
#define BATCH  16
#define TLEN   2048
#define MTOT   (BATCH*TLEN)   // 32768
#define KCONV  7
#define NCHUNK 16

// ---------------- scratch ----------------------------------------------------
__device__ float g_y[(size_t)MTOT * DIMC];      // conv out, then LN (tf32-rounded) in-place
__device__ float g_h[(size_t)MTOT * IDIM];      // GEMM1 out; k_apply rounds in-place
__device__ float g_y2[(size_t)MTOT * DIMC];     // GEMM2 out
__device__ float g_part[NCHUNK * BATCH * IDIM]; // GRN partial sums
__device__ float g_alpha[BATCH * IDIM];         // GRN fused scale
__device__ float g_w1[(size_t)IDIM * DIMC];     // tf32-rounded w1
__device__ float g_w2[(size_t)DIMC * IDIM];     // tf32-rounded w2

// ---------------- helpers ----------------------------------------------------
__device__ __forceinline__ uint32_t f2tf(float x) {
    uint32_t r; asm("cvt.rna.tf32.f32 %0, %1;" : "=r"(r) : "f"(x)); return r;
}
__device__ __forceinline__ float f2tf_f(float x) { return __uint_as_float(f2tf(x)); }
__device__ __forceinline__ void mma8(float* d, const uint32_t* a, const uint32_t* b) {
    asm volatile("mma.sync.aligned.m16n8k8.row.col.f32.tf32.tf32.f32 "
        "{%0,%1,%2,%3}, {%4,%5,%6,%7}, {%8,%9}, {%0,%1,%2,%3};\n"
        : "+f"(d[0]), "+f"(d[1]), "+f"(d[2]), "+f"(d[3])
        : "r"(a[0]), "r"(a[1]), "r"(a[2]), "r"(a[3]), "r"(b[0]), "r"(b[1]));
}
__device__ __forceinline__ void ldsm4(uint32_t* q, uint32_t addr) {
    asm volatile("ldmatrix.sync.aligned.m8n8.x4.shared.b16 {%0,%1,%2,%3}, [%4];"
        : "=r"(q[0]), "=r"(q[1]), "=r"(q[2]), "=r"(q[3]) : "r"(addr));
}
__device__ __forceinline__ float gelu_exact(float x) {
    return 0.5f * x * (1.f + erff(x * 0.70710678118654752440f));
}
__device__ __forceinline__ uint32_t smem_u32(const void* p) {
    uint32_t a;
    asm("{ .reg .u64 t; cvta.to.shared.u64 t, %1; cvt.u32.u64 %0, t; }" : "=r"(a) : "l"(p));
    return a;
}
__device__ __forceinline__ void cpa16(uint32_t d, const void* s) {
    asm volatile("cp.async.cg.shared.global [%0], [%1], 16;" :: "r"(d), "l"(s) : "memory");
}

// ---------------- 0. pre-round weights to tf32 -------------------------------
__global__ void k_cvtw(const float* __restrict__ w1, const float* __restrict__ w2) {
    const int i = blockIdx.x * 256 + threadIdx.x;           // float4 index
    const float4* src = (blockIdx.y == 0) ? (const float4*)w1 : (const float4*)w2;
    float4* dst = (blockIdx.y == 0) ? (float4*)g_w1 : (float4*)g_w2;
    float4 v = src[i];
    v.x = f2tf_f(v.x); v.y = f2tf_f(v.y); v.z = f2tf_f(v.z); v.w = f2tf_f(v.w);
    dst[i] = v;
}

// ---------------- 1. depthwise conv + bias + transpose ----------------------
__global__ void k_dwconv(const float* __restrict__ x, const float* __restrict__ w,
                         const float* __restrict__ bias) {
    __shared__ float sx[32][41];
    const int t0 = blockIdx.x * 32;
    const int c0 = blockIdx.y * 32;
    const int bb = blockIdx.z;
    const int tx = threadIdx.x;
    const int ty = threadIdx.y;
    const float* xb = x + ((size_t)bb * DIMC + c0) * TLEN;

#pragma unroll
    for (int j = 0; j < 4; j++) {
        int c = ty + j * 8;
        int t = t0 - 3 + tx;
        sx[c][tx] = (t >= 0 && t < TLEN) ? xb[(size_t)c * TLEN + t] : 0.f;
        if (tx < 6) {
            int t2 = t0 + 29 + tx;
            sx[c][32 + tx] = (t2 >= 0 && t2 < TLEN) ? xb[(size_t)c * TLEN + t2] : 0.f;
        }
    }
    __syncthreads();

    const int c = c0 + tx;
    float wr[KCONV];
#pragma unroll
    for (int k = 0; k < KCONV; k++) wr[k] = w[c * KCONV + k];
    const float bv = bias[c];

#pragma unroll
    for (int j = 0; j < 4; j++) {
        int tl = ty * 4 + j;
        float acc = bv;
#pragma unroll
        for (int k = 0; k < KCONV; k++) acc += wr[k] * sx[tx][tl + k];
        g_y[((size_t)bb * TLEN + t0 + tl) * DIMC + c] = acc;
    }
}

// ---------------- 2. LayerNorm over C, tf32-rounded output -------------------
__global__ void k_ln(const float* __restrict__ gam, const float* __restrict__ bet) {
    const size_t row = blockIdx.x;
    float4* p = (float4*)(g_y + row * DIMC);
    const int tid = threadIdx.x;
    float4 v = p[tid];
    float s = v.x + v.y + v.z + v.w;
    float q = v.x * v.x + v.y * v.y + v.z * v.z + v.w * v.w;
#pragma unroll
    for (int o = 16; o; o >>= 1) {
        s += __shfl_xor_sync(0xffffffffu, s, o);
        q += __shfl_xor_sync(0xffffffffu, q, o);
    }
    __shared__ float sh[8];
    if ((tid & 31) == 0) { sh[tid >> 5] = s; sh[(tid >> 5) + 4] = q; }
    __syncthreads();
    const float S = sh[0] + sh[1] + sh[2] + sh[3];
    const float Q = sh[4] + sh[5] + sh[6] + sh[7];
    const float mu = S * (1.f / DIMC);
    const float var = Q * (1.f / DIMC) - mu * mu;
    const float inv = rsqrtf(var + 1e-6f);
    const float4 gg = ((const float4*)gam)[tid];
    const float4 bb = ((const float4*)bet)[tid];
    v.x = f2tf_f((v.x - mu) * inv * gg.x + bb.x);
    v.y = f2tf_f((v.y - mu) * inv * gg.y + bb.y);
    v.z = f2tf_f((v.z - mu) * inv * gg.z + bb.z);
    v.w = f2tf_f((v.w - mu) * inv * gg.w + bb.w);
    p[tid] = v;
}

// ---------------- 3/5. TF32 mma.sync GEMM: cp.async + ldmatrix ---------------
// Operands are pre-rounded to tf32; mainloop has NO cvt and NO fragment fma.
// SEL==0: g_h  = GELU(g_y * g_w1^T + b1)        (K=512,  N=1536)
// SEL==1: g_y2 = g_h * g_w2^T + b2              (K=1536, N=512)
template <int SEL>
__global__ __launch_bounds__(256, 2)
void k_gemm(const float* __restrict__ bias) {
    constexpr int K    = (SEL == 0) ? DIMC : IDIM;
    constexpr int N    = (SEL == 0) ? IDIM : DIMC;
    constexpr int KT   = K / 16;
    constexpr int BKP  = 20;                 // 80B rows: 16B-aligned, LDSM conflict-free
    constexpr int STG  = 4;
    constexpr int STW  = 128 * BKP;          // floats per stage per operand
    constexpr uint32_t STGB = STW * 4;       // bytes per stage
    const float* __restrict__ A = (SEL == 0) ? g_y : g_h;
    const float* __restrict__ B = (SEL == 0) ? g_w1 : g_w2;
    float* __restrict__ C = (SEL == 0) ? g_h : g_y2;

    extern __shared__ float sm[];
    float* sA = sm;
    float* sB = sm + STG * STW;

    const int tid  = threadIdx.x;
    const int lane = tid & 31;
    const int warp = tid >> 5;
    const int wm = warp >> 2;                // 0..1 -> 64-row half
    const int wn = warp & 3;                 // 0..3 -> 32-col quarter
    const int m0 = blockIdx.y * 128;
    const int n0 = blockIdx.x * 128;

    // ---- cp.async fill addressing ----
    const int frow = tid >> 2;               // 0..63
    const int fcol = tid & 3;                // float4 slot
    const float* Ag = A + (size_t)(m0 + frow) * K + fcol * 4;
    const float* Bg = B + (size_t)(n0 + frow) * K + fcol * 4;
    const uint32_t smb = smem_u32(sm);
    const uint32_t fillA = smb + ((uint32_t)(frow * BKP + fcol * 4)) * 4;
    const uint32_t fillB = fillA + STG * STGB;

    auto fill = [&](int kt) {
        const uint32_t sto = (uint32_t)(kt & 3) * STGB;
        const float* ga = Ag + kt * 16;
        cpa16(fillA + sto, ga);
        cpa16(fillA + sto + 64 * BKP * 4, ga + (size_t)64 * K);
        const float* gb = Bg + kt * 16;
        cpa16(fillB + sto, gb);
        cpa16(fillB + sto + 64 * BKP * 4, gb + (size_t)64 * K);
        asm volatile("cp.async.commit_group;" ::: "memory");
    };

    // ---- ldmatrix per-lane base addresses ----
    const uint32_t t8 = lane >> 3, r8 = lane & 7;
    const uint32_t colb = (t8 >> 1) * 16;                     // bytes: +0 or +4 floats
    const uint32_t rowA = (uint32_t)(wm * 64) + (t8 & 1) * 8 + r8;
    const uint32_t rowB = (uint32_t)(wn * 32) + (t8 & 1) * 8 + r8;
    const uint32_t aAddr0 = smb + rowA * (BKP * 4) + colb;
    const uint32_t bAddr0 = smb + STG * STGB + rowB * (BKP * 4) + colb;

    float acc[4][4][4];
#pragma unroll
    for (int i = 0; i < 4; i++)
#pragma unroll
        for (int j = 0; j < 4; j++)
#pragma unroll
            for (int l = 0; l < 4; l++) acc[i][j][l] = 0.f;

    fill(0); fill(1); fill(2);

    for (int kt = 0; kt < KT; kt++) {
        asm volatile("cp.async.wait_group 2;" ::: "memory");
        __syncthreads();
        if (kt + 3 < KT) fill(kt + 3);
        else asm volatile("cp.async.commit_group;" ::: "memory");

        const uint32_t sto = (uint32_t)(kt & 3) * STGB;
#pragma unroll
        for (int ks = 0; ks < 2; ks++) {
            const uint32_t ko = sto + (uint32_t)ks * 32;
            uint32_t af[4][4], bf[2][4];
#pragma unroll
            for (int mt = 0; mt < 4; mt++)
                ldsm4(af[mt], aAddr0 + ko + (uint32_t)mt * (16 * BKP * 4));
#pragma unroll
            for (int np = 0; np < 2; np++)
                ldsm4(bf[np], bAddr0 + ko + (uint32_t)np * (16 * BKP * 4));
            // bf[np] = { b0[n=np*2], b0[n=np*2+1], b1[n=np*2], b1[n=np*2+1] }
#pragma unroll
            for (int mt = 0; mt < 4; mt++)
#pragma unroll
                for (int np = 0; np < 2; np++) {
                    uint32_t b0[2] = { bf[np][0], bf[np][2] };
                    uint32_t b1[2] = { bf[np][1], bf[np][3] };
                    mma8(acc[mt][2 * np], af[mt], b0);
                    mma8(acc[mt][2 * np + 1], af[mt], b1);
                }
        }
    }

    // epilogue (verified layout)
#pragma unroll
    for (int mt = 0; mt < 4; mt++) {
        int row = m0 + wm * 64 + mt * 16 + (lane >> 2);
#pragma unroll
        for (int nt = 0; nt < 4; nt++) {
            int col = n0 + wn * 32 + nt * 8 + 2 * (lane & 3);
            float b0v = bias[col], b1v = bias[col + 1];
            float v0 = acc[mt][nt][0] + b0v;
            float v1 = acc[mt][nt][1] + b1v;
            float v2 = acc[mt][nt][2] + b0v;
            float v3 = acc[mt][nt][3] + b1v;
            if (SEL == 0) {
                v0 = gelu_exact(v0); v1 = gelu_exact(v1);
                v2 = gelu_exact(v2); v3 = gelu_exact(v3);
            }
            *(float2*)&C[(size_t)row * N + col] = make_float2(v0, v1);
            *(float2*)&C[(size_t)(row + 8) * N + col] = make_float2(v2, v3);
        }
    }
}

// ---------------- 4a. GRN partial sums ---------------------------------------
__global__ void k_grn_partial() {
    const int i = blockIdx.x * 256 + threadIdx.x;
    const int tc = blockIdx.y;
    const int b = blockIdx.z;
    constexpr int TC = TLEN / NCHUNK;               // 128
    const float* p = g_h + ((size_t)b * TLEN + tc * TC) * IDIM + i;
    float s = 0.f;
#pragma unroll 8
    for (int t = 0; t < TC; t++) {
        float v = p[(size_t)t * IDIM];
        s += v * v;
    }
    g_part[((size_t)tc * BATCH + b) * IDIM + i] = s;
}

// ---------------- 4b. GRN alpha ----------------------------------------------
__global__ void k_grn_alpha(const float* __restrict__ gg) {
    const int b = blockIdx.x;
    const int tid = threadIdx.x;
    __shared__ float sgx[IDIM];
    __shared__ float red[8];
    float local = 0.f;
    for (int i = tid; i < IDIM; i += 256) {
        float s = 0.f;
#pragma unroll
        for (int tc = 0; tc < NCHUNK; tc++)
            s += g_part[((size_t)tc * BATCH + b) * IDIM + i];
        float gx = sqrtf(s);
        sgx[i] = gx;
        local += gx;
    }
#pragma unroll
    for (int o = 16; o; o >>= 1) local += __shfl_xor_sync(0xffffffffu, local, o);
    if ((tid & 31) == 0) red[tid >> 5] = local;
    __syncthreads();
    float tot = red[0] + red[1] + red[2] + red[3] + red[4] + red[5] + red[6] + red[7];
    const float inv = 1.f / (tot * (1.f / IDIM) + 1e-6f);
    for (int i = tid; i < IDIM; i += 256)
        g_alpha[b * IDIM + i] = 1.f + gg[i] * sgx[i] * inv;
}

// ---------------- 4c. apply GRN affine in place, tf32-rounded -----------------
__global__ void k_apply(const float* __restrict__ grn_b) {
    const int b = blockIdx.y;
    const int t0 = blockIdx.x * 8;
    const int tid = threadIdx.x;    // 384: one float4 each over IDIM
    float4 al = ((const float4*)(g_alpha + (size_t)b * IDIM))[tid];
    float4 be = ((const float4*)grn_b)[tid];
    float4* row = (float4*)(g_h + ((size_t)b * TLEN + t0) * IDIM) + tid;
#pragma unroll
    for (int j = 0; j < 8; j++) {
        float4 v = row[(size_t)j * (IDIM / 4)];
        v.x = f2tf_f(fmaf(v.x, al.x, be.x));
        v.y = f2tf_f(fmaf(v.y, al.y, be.y));
        v.z = f2tf_f(fmaf(v.z, al.z, be.z));
        v.w = f2tf_f(fmaf(v.w, al.w, be.w));
        row[(size_t)j * (IDIM / 4)] = v;
    }
}

// ---------------- 6. transpose + residual ------------------------------------
__global__ void k_out(const float* __restrict__ x, float* __restrict__ out) {
    __shared__ float s[32][33];
    const int t0 = blockIdx.x * 32;
    const int c0 = blockIdx.y * 32;
    const int b = blockIdx.z;
    const int tx = threadIdx.x, ty = threadIdx.y;
#pragma unroll
    for (int j = 0; j < 4; j++) {
        int t = ty + j * 8;
        s[t][tx] = g_y2[((size_t)b * TLEN + t0 + t) * DIMC + c0 + tx];
    }
    __syncthreads();
#pragma unroll
    for (int j = 0; j < 4; j++) {
        int c = ty + j * 8;
        size_t o = ((size_t)b * DIMC + c0 + c) * TLEN + t0 + tx;
        out[o] = x[o] + s[tx][c];
    }
}

// ---------------- launch ------------------------------------------------------
extern "C" void kernel_launch(void* const* d_in, const int* in_sizes, int n_in,
                              void* d_out, int out_size) {
    (void)in_sizes; (void)n_in; (void)out_size;
    const float* x     = (const float*)d_in[0];
    const float* dw_w  = (const float*)d_in[1];
    const float* dw_b  = (const float*)d_in[2];
    const float* ln_g  = (const float*)d_in[3];
    const float* ln_b  = (const float*)d_in[4];
    const float* w1    = (const float*)d_in[5];
    const float* b1    = (const float*)d_in[6];
    const float* grn_g = (const float*)d_in[7];
    const float* grn_b = (const float*)d_in[8];
    const float* w2    = (const float*)d_in[9];
    const float* b2    = (const float*)d_in[10];
    float* out = (float*)d_out;

    const int dyn = 2 * 4 * 128 * 20 * 4;               // 81920
    cudaFuncSetAttribute(k_gemm<0>, cudaFuncAttributeMaxDynamicSharedMemorySize, dyn);
    cudaFuncSetAttribute(k_gemm<1>, cudaFuncAttributeMaxDynamicSharedMemorySize, dyn);

    k_cvtw<<<dim3(IDIM * DIMC / 4 / 256, 2), 256>>>(w1, w2);
    k_dwconv<<<dim3(TLEN / 32, DIMC / 32, BATCH), dim3(32, 8)>>>(x, dw_w, dw_b);
    k_ln<<<MTOT, 128>>>(ln_g, ln_b);
    k_gemm<0><<<dim3(IDIM / 128, MTOT / 128), 256, dyn>>>(b1);
    k_grn_partial<<<dim3(IDIM / 256, NCHUNK, BATCH), 256>>>();
    k_grn_alpha<<<BATCH, 256>>>(grn_g);
    k_apply<<<dim3(TLEN / 8, BATCH), 384>>>(grn_b);
    k_gemm<1><<<dim3(DIMC / 128, MTOT / 128), 256, dyn>>>(b2);
    k_out<<<dim3(TLEN / 32, DIMC / 32, BATCH), dim3(32, 8)>>>(x, out);
}

// round 7
// speedup vs baseline: 1.5240x; 1.2100x over previous
#include <cuda_runtime.h>
#include <cstdint>

#define DIMC   512
#define IDIM   1536
#define BATCH  16
#define TLEN   2048
#define MTOT   (BATCH*TLEN)   // 32768
#define KCONV  7
#define NCHUNK 16

// ---------------- scratch ----------------------------------------------------
__device__ float g_y[(size_t)MTOT * DIMC];      // conv out, then LN (tf32-rounded) in-place
__device__ float g_h[(size_t)MTOT * IDIM];      // GEMM1 out; k_apply rounds in-place
__device__ float g_y2[(size_t)MTOT * DIMC];     // GEMM2 out
__device__ float g_part[NCHUNK * BATCH * IDIM]; // GRN partial sums
__device__ float g_alpha[BATCH * IDIM];         // GRN fused scale
__device__ float g_w1[(size_t)IDIM * DIMC];     // tf32-rounded w1
__device__ float g_w2[(size_t)DIMC * IDIM];     // tf32-rounded w2

// ---------------- helpers ----------------------------------------------------
__device__ __forceinline__ uint32_t f2tf(float x) {
    uint32_t r; asm("cvt.rna.tf32.f32 %0, %1;" : "=r"(r) : "f"(x)); return r;
}
__device__ __forceinline__ float f2tf_f(float x) { return __uint_as_float(f2tf(x)); }
__device__ __forceinline__ void mma8(float* d, const uint32_t* a, const uint32_t* b) {
    asm volatile("mma.sync.aligned.m16n8k8.row.col.f32.tf32.tf32.f32 "
        "{%0,%1,%2,%3}, {%4,%5,%6,%7}, {%8,%9}, {%0,%1,%2,%3};\n"
        : "+f"(d[0]), "+f"(d[1]), "+f"(d[2]), "+f"(d[3])
        : "r"(a[0]), "r"(a[1]), "r"(a[2]), "r"(a[3]), "r"(b[0]), "r"(b[1]));
}
__device__ __forceinline__ void ldsm4(uint32_t* q, uint32_t addr) {
    asm volatile("ldmatrix.sync.aligned.m8n8.x4.shared.b16 {%0,%1,%2,%3}, [%4];"
        : "=r"(q[0]), "=r"(q[1]), "=r"(q[2]), "=r"(q[3]) : "r"(addr));
}
__device__ __forceinline__ float gelu_exact(float x) {
    return 0.5f * x * (1.f + erff(x * 0.70710678118654752440f));
}
__device__ __forceinline__ uint32_t smem_u32(const void* p) {
    uint32_t a;
    asm("{ .reg .u64 t; cvta.to.shared.u64 t, %1; cvt.u32.u64 %0, t; }" : "=r"(a) : "l"(p));
    return a;
}
__device__ __forceinline__ void cpa16(uint32_t d, const void* s) {
    asm volatile("cp.async.cg.shared.global [%0], [%1], 16;" :: "r"(d), "l"(s) : "memory");
}

// ---------------- 0. pre-round weights to tf32 -------------------------------
__global__ void k_cvtw(const float* __restrict__ w1, const float* __restrict__ w2) {
    const int i = blockIdx.x * 256 + threadIdx.x;
    const float4* src = (blockIdx.y == 0) ? (const float4*)w1 : (const float4*)w2;
    float4* dst = (blockIdx.y == 0) ? (float4*)g_w1 : (float4*)g_w2;
    float4 v = src[i];
    v.x = f2tf_f(v.x); v.y = f2tf_f(v.y); v.z = f2tf_f(v.z); v.w = f2tf_f(v.w);
    dst[i] = v;
}

// ---------------- 1. depthwise conv + bias + transpose ----------------------
__global__ void k_dwconv(const float* __restrict__ x, const float* __restrict__ w,
                         const float* __restrict__ bias) {
    __shared__ float sx[32][41];
    const int t0 = blockIdx.x * 32;
    const int c0 = blockIdx.y * 32;
    const int bb = blockIdx.z;
    const int tx = threadIdx.x;
    const int ty = threadIdx.y;
    const float* xb = x + ((size_t)bb * DIMC + c0) * TLEN;

#pragma unroll
    for (int j = 0; j < 4; j++) {
        int c = ty + j * 8;
        int t = t0 - 3 + tx;
        sx[c][tx] = (t >= 0 && t < TLEN) ? xb[(size_t)c * TLEN + t] : 0.f;
        if (tx < 6) {
            int t2 = t0 + 29 + tx;
            sx[c][32 + tx] = (t2 >= 0 && t2 < TLEN) ? xb[(size_t)c * TLEN + t2] : 0.f;
        }
    }
    __syncthreads();

    const int c = c0 + tx;
    float wr[KCONV];
#pragma unroll
    for (int k = 0; k < KCONV; k++) wr[k] = w[c * KCONV + k];
    const float bv = bias[c];

#pragma unroll
    for (int j = 0; j < 4; j++) {
        int tl = ty * 4 + j;
        float acc = bv;
#pragma unroll
        for (int k = 0; k < KCONV; k++) acc += wr[k] * sx[tx][tl + k];
        g_y[((size_t)bb * TLEN + t0 + tl) * DIMC + c] = acc;
    }
}

// ---------------- 2. LayerNorm over C, tf32-rounded output -------------------
__global__ void k_ln(const float* __restrict__ gam, const float* __restrict__ bet) {
    const size_t row = blockIdx.x;
    float4* p = (float4*)(g_y + row * DIMC);
    const int tid = threadIdx.x;
    float4 v = p[tid];
    float s = v.x + v.y + v.z + v.w;
    float q = v.x * v.x + v.y * v.y + v.z * v.z + v.w * v.w;
#pragma unroll
    for (int o = 16; o; o >>= 1) {
        s += __shfl_xor_sync(0xffffffffu, s, o);
        q += __shfl_xor_sync(0xffffffffu, q, o);
    }
    __shared__ float sh[8];
    if ((tid & 31) == 0) { sh[tid >> 5] = s; sh[(tid >> 5) + 4] = q; }
    __syncthreads();
    const float S = sh[0] + sh[1] + sh[2] + sh[3];
    const float Q = sh[4] + sh[5] + sh[6] + sh[7];
    const float mu = S * (1.f / DIMC);
    const float var = Q * (1.f / DIMC) - mu * mu;
    const float inv = rsqrtf(var + 1e-6f);
    const float4 gg = ((const float4*)gam)[tid];
    const float4 bb = ((const float4*)bet)[tid];
    v.x = f2tf_f((v.x - mu) * inv * gg.x + bb.x);
    v.y = f2tf_f((v.y - mu) * inv * gg.y + bb.y);
    v.z = f2tf_f((v.z - mu) * inv * gg.z + bb.z);
    v.w = f2tf_f((v.w - mu) * inv * gg.w + bb.w);
    p[tid] = v;
}

// ---------------- 3/5. TF32 mma.sync GEMM: K-stage 32, swizzled, pipelined ---
// SEL==0: g_h  = GELU(g_y * g_w1^T + b1)        (K=512,  N=1536)
// SEL==1: g_y2 = g_h * g_w2^T + b2              (K=1536, N=512)
template <int SEL>
__global__ __launch_bounds__(256, 2)
void k_gemm(const float* __restrict__ bias) {
    constexpr int K   = (SEL == 0) ? DIMC : IDIM;
    constexpr int N   = (SEL == 0) ? IDIM : DIMC;
    constexpr int KT  = K / 32;
    constexpr int STG = 3;
    constexpr uint32_t STGB = 128 * 128;     // 16KB: 128 rows x 32 floats
    const float* __restrict__ A = (SEL == 0) ? g_y : g_h;
    const float* __restrict__ B = (SEL == 0) ? g_w1 : g_w2;
    float* __restrict__ C = (SEL == 0) ? g_h : g_y2;

    extern __shared__ float sm[];
    const uint32_t smb = smem_u32(sm);
    const uint32_t smA = smb;
    const uint32_t smB = smb + STG * STGB;

    const int tid  = threadIdx.x;
    const int lane = tid & 31;
    const int warp = tid >> 5;
    const int wm = warp >> 2;                // 0..1 -> 64-row half
    const int wn = warp & 3;                 // 0..3 -> 32-col quarter
    const int m0 = blockIdx.y * 128;
    const int n0 = blockIdx.x * 128;

    // ---- fill addressing: thread j-th chunk differs by exactly 32 rows ----
    const int row0 = tid >> 3;               // 0..31
    const int cch  = tid & 7;                // 16B chunk within 128B row
    const uint32_t sOff0 = (uint32_t)row0 * 128 + ((uint32_t)(cch ^ (row0 & 7)) << 4);
    const float* gA = A + (size_t)(m0 + row0) * K + cch * 4;
    const float* gB = B + (size_t)(n0 + row0) * K + cch * 4;

    int fillSt = 0;
    auto fill = [&]() {
        const uint32_t sto = (uint32_t)fillSt * STGB;
#pragma unroll
        for (int j = 0; j < 4; j++) {
            cpa16(smA + sto + sOff0 + 4096u * j, gA + (size_t)(32 * j) * K);
            cpa16(smB + sto + sOff0 + 4096u * j, gB + (size_t)(32 * j) * K);
        }
        gA += 32; gB += 32;
        fillSt = (fillSt == 2) ? 0 : fillSt + 1;
        asm volatile("cp.async.commit_group;" ::: "memory");
    };

    // ---- ldmatrix addressing (swizzled) ----
    const uint32_t t8 = lane >> 3, r8 = lane & 7;
    const uint32_t chalf = t8 >> 1;          // chunk half within k8
    const uint32_t rsel = (t8 & 1) * 8;
    uint32_t xoff[4];
#pragma unroll
    for (int ks = 0; ks < 4; ks++)
        xoff[ks] = ((uint32_t)((2 * ks + chalf) ^ r8)) << 4;
    const uint32_t aBase = smA + ((uint32_t)(wm * 64) + rsel + r8) * 128;
    const uint32_t bBase = smB + ((uint32_t)(wn * 32) + rsel + r8) * 128;

    float acc[4][4][4];
#pragma unroll
    for (int i = 0; i < 4; i++)
#pragma unroll
        for (int j = 0; j < 4; j++)
#pragma unroll
            for (int l = 0; l < 4; l++) acc[i][j][l] = 0.f;

    fill(); fill();

    int cmpSt = 0;
    for (int kt = 0; kt < KT; kt++) {
        asm volatile("cp.async.wait_group 1;" ::: "memory");
        __syncthreads();
        if (kt + 2 < KT) fill();
        else asm volatile("cp.async.commit_group;" ::: "memory");

        const uint32_t aS = aBase + (uint32_t)cmpSt * STGB;
        const uint32_t bS = bBase + (uint32_t)cmpSt * STGB;
        cmpSt = (cmpSt == 2) ? 0 : cmpSt + 1;

#pragma unroll
        for (int ks = 0; ks < 4; ks++) {
            uint32_t af[4][4], bf[2][4];
#pragma unroll
            for (int mt = 0; mt < 4; mt++)
                ldsm4(af[mt], aS + (uint32_t)mt * 2048 + xoff[ks]);
#pragma unroll
            for (int np = 0; np < 2; np++)
                ldsm4(bf[np], bS + (uint32_t)np * 2048 + xoff[ks]);
#pragma unroll
            for (int mt = 0; mt < 4; mt++)
#pragma unroll
                for (int np = 0; np < 2; np++) {
                    uint32_t b0[2] = { bf[np][0], bf[np][2] };
                    uint32_t b1[2] = { bf[np][1], bf[np][3] };
                    mma8(acc[mt][2 * np], af[mt], b0);
                    mma8(acc[mt][2 * np + 1], af[mt], b1);
                }
        }
    }

    // epilogue (verified layout)
#pragma unroll
    for (int mt = 0; mt < 4; mt++) {
        int row = m0 + wm * 64 + mt * 16 + (lane >> 2);
#pragma unroll
        for (int nt = 0; nt < 4; nt++) {
            int col = n0 + wn * 32 + nt * 8 + 2 * (lane & 3);
            float b0v = bias[col], b1v = bias[col + 1];
            float v0 = acc[mt][nt][0] + b0v;
            float v1 = acc[mt][nt][1] + b1v;
            float v2 = acc[mt][nt][2] + b0v;
            float v3 = acc[mt][nt][3] + b1v;
            if (SEL == 0) {
                v0 = gelu_exact(v0); v1 = gelu_exact(v1);
                v2 = gelu_exact(v2); v3 = gelu_exact(v3);
            }
            *(float2*)&C[(size_t)row * N + col] = make_float2(v0, v1);
            *(float2*)&C[(size_t)(row + 8) * N + col] = make_float2(v2, v3);
        }
    }
}

// ---------------- 4a. GRN partial sums ---------------------------------------
__global__ void k_grn_partial() {
    const int i = blockIdx.x * 256 + threadIdx.x;
    const int tc = blockIdx.y;
    const int b = blockIdx.z;
    constexpr int TC = TLEN / NCHUNK;               // 128
    const float* p = g_h + ((size_t)b * TLEN + tc * TC) * IDIM + i;
    float s = 0.f;
#pragma unroll 8
    for (int t = 0; t < TC; t++) {
        float v = p[(size_t)t * IDIM];
        s += v * v;
    }
    g_part[((size_t)tc * BATCH + b) * IDIM + i] = s;
}

// ---------------- 4b. GRN alpha ----------------------------------------------
__global__ void k_grn_alpha(const float* __restrict__ gg) {
    const int b = blockIdx.x;
    const int tid = threadIdx.x;
    __shared__ float sgx[IDIM];
    __shared__ float red[8];
    float local = 0.f;
    for (int i = tid; i < IDIM; i += 256) {
        float s = 0.f;
#pragma unroll
        for (int tc = 0; tc < NCHUNK; tc++)
            s += g_part[((size_t)tc * BATCH + b) * IDIM + i];
        float gx = sqrtf(s);
        sgx[i] = gx;
        local += gx;
    }
#pragma unroll
    for (int o = 16; o; o >>= 1) local += __shfl_xor_sync(0xffffffffu, local, o);
    if ((tid & 31) == 0) red[tid >> 5] = local;
    __syncthreads();
    float tot = red[0] + red[1] + red[2] + red[3] + red[4] + red[5] + red[6] + red[7];
    const float inv = 1.f / (tot * (1.f / IDIM) + 1e-6f);
    for (int i = tid; i < IDIM; i += 256)
        g_alpha[b * IDIM + i] = 1.f + gg[i] * sgx[i] * inv;
}

// ---------------- 4c. apply GRN affine in place, tf32-rounded -----------------
__global__ void k_apply(const float* __restrict__ grn_b) {
    const int b = blockIdx.y;
    const int t0 = blockIdx.x * 8;
    const int tid = threadIdx.x;    // 384: one float4 each over IDIM
    float4 al = ((const float4*)(g_alpha + (size_t)b * IDIM))[tid];
    float4 be = ((const float4*)grn_b)[tid];
    float4* row = (float4*)(g_h + ((size_t)b * TLEN + t0) * IDIM) + tid;
#pragma unroll
    for (int j = 0; j < 8; j++) {
        float4 v = row[(size_t)j * (IDIM / 4)];
        v.x = f2tf_f(fmaf(v.x, al.x, be.x));
        v.y = f2tf_f(fmaf(v.y, al.y, be.y));
        v.z = f2tf_f(fmaf(v.z, al.z, be.z));
        v.w = f2tf_f(fmaf(v.w, al.w, be.w));
        row[(size_t)j * (IDIM / 4)] = v;
    }
}

// ---------------- 6. transpose + residual ------------------------------------
__global__ void k_out(const float* __restrict__ x, float* __restrict__ out) {
    __shared__ float s[32][33];
    const int t0 = blockIdx.x * 32;
    const int c0 = blockIdx.y * 32;
    const int b = blockIdx.z;
    const int tx = threadIdx.x, ty = threadIdx.y;
#pragma unroll
    for (int j = 0; j < 4; j++) {
        int t = ty + j * 8;
        s[t][tx] = g_y2[((size_t)b * TLEN + t0 + t) * DIMC + c0 + tx];
    }
    __syncthreads();
#pragma unroll
    for (int j = 0; j < 4; j++) {
        int c = ty + j * 8;
        size_t o = ((size_t)b * DIMC + c0 + c) * TLEN + t0 + tx;
        out[o] = x[o] + s[tx][c];
    }
}

// ---------------- launch ------------------------------------------------------
extern "C" void kernel_launch(void* const* d_in, const int* in_sizes, int n_in,
                              void* d_out, int out_size) {
    (void)in_sizes; (void)n_in; (void)out_size;
    const float* x     = (const float*)d_in[0];
    const float* dw_w  = (const float*)d_in[1];
    const float* dw_b  = (const float*)d_in[2];
    const float* ln_g  = (const float*)d_in[3];
    const float* ln_b  = (const float*)d_in[4];
    const float* w1    = (const float*)d_in[5];
    const float* b1    = (const float*)d_in[6];
    const float* grn_g = (const float*)d_in[7];
    const float* grn_b = (const float*)d_in[8];
    const float* w2    = (const float*)d_in[9];
    const float* b2    = (const float*)d_in[10];
    float* out = (float*)d_out;

    const int dyn = 3 * 2 * 128 * 128;               // 98304
    cudaFuncSetAttribute(k_gemm<0>, cudaFuncAttributeMaxDynamicSharedMemorySize, dyn);
    cudaFuncSetAttribute(k_gemm<1>, cudaFuncAttributeMaxDynamicSharedMemorySize, dyn);

    k_cvtw<<<dim3(IDIM * DIMC / 4 / 256, 2), 256>>>(w1, w2);
    k_dwconv<<<dim3(TLEN / 32, DIMC / 32, BATCH), dim3(32, 8)>>>(x, dw_w, dw_b);
    k_ln<<<MTOT, 128>>>(ln_g, ln_b);
    k_gemm<0><<<dim3(IDIM / 128, MTOT / 128), 256, dyn>>>(b1);
    k_grn_partial<<<dim3(IDIM / 256, NCHUNK, BATCH), 256>>>();
    k_grn_alpha<<<BATCH, 256>>>(grn_g);
    k_apply<<<dim3(TLEN / 8, BATCH), 384>>>(grn_b);
    k_gemm<1><<<dim3(DIMC / 128, MTOT / 128), 256, dyn>>>(b2);
    k_out<<<dim3(TLEN / 32, DIMC / 32, BATCH), dim3(32, 8)>>>(x, out);
}